// round 1
// baseline (speedup 1.0000x reference)
#include <cuda_runtime.h>

// QuadraticNetCholesky fused kernel (sm_103a)
//   h1 = elu(x@W1^T + b1)   [fused into layer-2 k loop, never materialized]
//   h2 = elu(h1@W2^T + b2)
//   v  = softplus(h2@W3^T + b3)      (78 lower-tri elements)
//   out = L @ L^T  (L = tril scatter of v, 12x12)
// One thread per sample. Weights in smem (W2, W3 transposed + padded for
// LDS.128 uniform broadcasts). Packed f32x2 FMA (FFMA2) for 2x fp32 rate.
// Output staged in smem (stride 148 = 4*odd -> conflict-free) then drained
// with coalesced float4 stores.

#define TPB   256
#define NIN   12
#define H1    128
#define H2    32
#define TRI   78

typedef unsigned long long u64;

__device__ __forceinline__ u64 pk2(float lo, float hi) {
    u64 r;
    asm("mov.b64 %0, {%1, %2};" : "=l"(r) : "f"(lo), "f"(hi));
    return r;
}
__device__ __forceinline__ void unpk2(u64 v, float& lo, float& hi) {
    asm("mov.b64 {%0, %1}, %2;" : "=f"(lo), "=f"(hi) : "l"(v));
}
// packed 2xfp32 fma: d = a*b + c  (FFMA2 on sm_103a; PTX-only, ptxas won't auto-fuse)
__device__ __forceinline__ u64 fma2(u64 a, u64 b, u64 c) {
    u64 d;
    asm("fma.rn.f32x2 %0, %1, %2, %3;" : "=l"(d) : "l"(a), "l"(b), "l"(c));
    return d;
}

// smem layout (float offsets)
#define OFF_W1    0                       // [128][12]
#define OFF_B1    1536                    // [128]
#define OFF_W2T   1664                    // [128][32]  W2 transposed: [k][o]
#define OFF_B2    5760                    // [32]
#define OFF_W3T   5792                    // [32][80]   W3 transposed+padded: [j][t]
#define OFF_B3    8352                    // [80] (padded)
#define OFF_STG   8432                    // [TPB][148] output staging
#define STG_STRIDE 148                    // 4*37 (odd) -> conflict-free STS.128 phases
#define SMEM_FLOATS (OFF_STG + TPB * STG_STRIDE)   // 46320 floats = 185280 B

__global__ void __launch_bounds__(TPB, 1)
qnc_kernel(const float* __restrict__ x,
           const float* __restrict__ W1, const float* __restrict__ b1,
           const float* __restrict__ W2, const float* __restrict__ b2,
           const float* __restrict__ W3, const float* __restrict__ b3,
           float* __restrict__ out, int B)
{
    extern __shared__ float sm[];
    const int tid = threadIdx.x;

    // ---- cooperative weight load (coalesced gmem reads) ----
    for (int i = tid; i < H1 * NIN; i += TPB) sm[OFF_W1 + i] = W1[i];
    for (int i = tid; i < H1;       i += TPB) sm[OFF_B1 + i] = b1[i];
    for (int i = tid; i < H2 * H1;  i += TPB) {          // transpose W2 -> [k][o]
        int o = i >> 7, k = i & 127;
        sm[OFF_W2T + k * H2 + o] = W2[i];
    }
    for (int i = tid; i < H2;       i += TPB) sm[OFF_B2 + i] = b2[i];
    for (int i = tid; i < 32 * 80;  i += TPB) sm[OFF_W3T + i] = 0.f;  // zero pad
    for (int i = tid; i < 80;       i += TPB) sm[OFF_B3 + i] = 0.f;
    __syncthreads();
    for (int i = tid; i < TRI * H2; i += TPB) {          // transpose W3 -> [j][t], t padded to 80
        int t = i >> 5, j = i & 31;
        sm[OFF_W3T + j * 80 + t] = W3[i];
    }
    for (int i = tid; i < TRI;      i += TPB) sm[OFF_B3 + i] = b3[i];
    __syncthreads();

    const int sample = blockIdx.x * TPB + tid;
    if (sample < B) {
        // ---- load x (3x LDG.128; row is 48B, 16B-aligned) ----
        const float4* xv = reinterpret_cast<const float4*>(x + (size_t)sample * NIN);
        float4 xa = xv[0], xb = xv[1], xc = xv[2];
        u64 xp0 = pk2(xa.x, xa.y), xp1 = pk2(xa.z, xa.w);
        u64 xp2 = pk2(xb.x, xb.y), xp3 = pk2(xb.z, xb.w);
        u64 xp4 = pk2(xc.x, xc.y), xp5 = pk2(xc.z, xc.w);

        // h2 accumulators: 16 packed pairs over output neurons, init = b2
        u64 h2p[16];
#pragma unroll
        for (int p = 0; p < 16; p++)
            h2p[p] = *reinterpret_cast<const u64*>(&sm[OFF_B2 + 2 * p]);

        // ---- fused layer1 + layer2 over k ----
#pragma unroll 4
        for (int k = 0; k < H1; k++) {
            const float4* w1r = reinterpret_cast<const float4*>(&sm[OFF_W1 + k * NIN]);
            float4 wa = w1r[0], wb = w1r[1], wc = w1r[2];
            u64 acc = fma2(xp0, pk2(wa.x, wa.y), pk2(sm[OFF_B1 + k], 0.f));
            acc = fma2(xp1, pk2(wa.z, wa.w), acc);
            acc = fma2(xp2, pk2(wb.x, wb.y), acc);
            acc = fma2(xp3, pk2(wb.z, wb.w), acc);
            acc = fma2(xp4, pk2(wc.x, wc.y), acc);
            acc = fma2(xp5, pk2(wc.z, wc.w), acc);
            float a0, a1;
            unpk2(acc, a0, a1);
            float pre = a0 + a1;
            // elu (alpha=1): exp(x)-1 branchlessly; error ~1e-7 abs near 0, fine
            float h = pre > 0.f ? pre : (__expf(pre) - 1.f);
            u64 hd = pk2(h, h);
            const float4* w2r = reinterpret_cast<const float4*>(&sm[OFF_W2T + k * H2]);
#pragma unroll
            for (int m = 0; m < 8; m++) {
                float4 w = w2r[m];
                h2p[2 * m]     = fma2(hd, pk2(w.x, w.y), h2p[2 * m]);
                h2p[2 * m + 1] = fma2(hd, pk2(w.z, w.w), h2p[2 * m + 1]);
            }
        }

        // ---- elu + unpack h2 ----
        float h2s[32];
#pragma unroll
        for (int p = 0; p < 16; p++) {
            float e0, e1;
            unpk2(h2p[p], e0, e1);
            h2s[2 * p]     = e0 > 0.f ? e0 : (__expf(e0) - 1.f);
            h2s[2 * p + 1] = e1 > 0.f ? e1 : (__expf(e1) - 1.f);
        }

        // ---- layer 3: 39 packed pairs over the 78 outputs ----
        u64 vacc[39];
#pragma unroll
        for (int p = 0; p < 39; p++)
            vacc[p] = *reinterpret_cast<const u64*>(&sm[OFF_B3 + 2 * p]);
#pragma unroll
        for (int j = 0; j < H2; j++) {
            u64 hj = pk2(h2s[j], h2s[j]);
            const float4* wr = reinterpret_cast<const float4*>(&sm[OFF_W3T + j * 80]);
#pragma unroll
            for (int q = 0; q < 19; q++) {        // t = 4q .. 4q+3  (0..75)
                float4 w = wr[q];
                vacc[2 * q]     = fma2(hj, pk2(w.x, w.y), vacc[2 * q]);
                vacc[2 * q + 1] = fma2(hj, pk2(w.z, w.w), vacc[2 * q + 1]);
            }
            float2 wt = *reinterpret_cast<const float2*>(&sm[OFF_W3T + j * 80 + 76]);
            vacc[38] = fma2(hj, pk2(wt.x, wt.y), vacc[38]);   // t = 76,77
        }

        // ---- softplus (stable: max(x,0)+log1p(exp(-|x|))) -> L (tri, row-major) ----
        float Lr[TRI];
#pragma unroll
        for (int p = 0; p < 39; p++) {
            float v0, v1;
            unpk2(vacc[p], v0, v1);
            Lr[2 * p]     = fmaxf(v0, 0.f) + log1pf(__expf(-fabsf(v0)));
            Lr[2 * p + 1] = fmaxf(v1, 0.f) + log1pf(__expf(-fabsf(v1)));
        }

        // ---- M = L L^T, staged to smem (conflict-free STS.128) ----
        const int sbase = OFF_STG + tid * STG_STRIDE;
#pragma unroll
        for (int r = 0; r < 12; r++) {
            float row[12];
#pragma unroll
            for (int c = 0; c < 12; c++) {
                const int mn = (r < c) ? r : c;
                const int ro = r * (r + 1) / 2, co = c * (c + 1) / 2;
                float s = Lr[ro] * Lr[co];
#pragma unroll
                for (int j = 1; j <= mn; j++)
                    s = fmaf(Lr[ro + j], Lr[co + j], s);
                row[c] = s;
            }
#pragma unroll
            for (int c4 = 0; c4 < 12; c4 += 4)
                *reinterpret_cast<float4*>(&sm[sbase + r * 12 + c4]) =
                    make_float4(row[c4], row[c4 + 1], row[c4 + 2], row[c4 + 3]);
        }
    }
    __syncthreads();

    // ---- coalesced drain: smem staging -> gmem ----
    const int TOT4 = TPB * 144 / 4;                         // 9216 float4 per CTA
    float4* outv = reinterpret_cast<float4*>(out) + (size_t)blockIdx.x * TOT4;
    const long long lim4 = (long long)B * 36;
    for (int q = tid; q < TOT4; q += TPB) {
        long long gq = (long long)blockIdx.x * TOT4 + q;
        if (gq < lim4) {
            int sl = q / 36, o4 = q - sl * 36;
            outv[q] = *reinterpret_cast<const float4*>(&sm[OFF_STG + sl * STG_STRIDE + o4 * 4]);
        }
    }
}

extern "C" void kernel_launch(void* const* d_in, const int* in_sizes, int n_in,
                              void* d_out, int out_size)
{
    const float* x  = (const float*)d_in[0];
    const float* W1 = (const float*)d_in[1];
    const float* b1 = (const float*)d_in[2];
    const float* W2 = (const float*)d_in[3];
    const float* b2 = (const float*)d_in[4];
    const float* W3 = (const float*)d_in[5];
    const float* b3 = (const float*)d_in[6];

    const int B = in_sizes[0] / NIN;                        // 262144
    const int grid = (B + TPB - 1) / TPB;                   // 1024
    const size_t smem = SMEM_FLOATS * sizeof(float);        // ~185 KB

    cudaFuncSetAttribute(qnc_kernel, cudaFuncAttributeMaxDynamicSharedMemorySize, (int)smem);
    qnc_kernel<<<grid, TPB, smem>>>(x, W1, b1, W2, b2, W3, b3, (float*)d_out, B);
}

// round 3
// speedup vs baseline: 1.2613x; 1.2613x over previous
#include <cuda_runtime.h>
#include <cuda_bf16.h>
#include <cstdint>

// QuadraticNetCholesky via warp-level mma.sync (HMMA, bf16x3 split) on sm_103.
// Per warp: 16 samples. D-fragment of layer k == A-fragment of layer k+1
// (in-register repack, no shuffles).
//   GEMM1: [16x16]x[16x128]  (K=12 + bias col + pad)
//   GEMM2: [16x128]x[128x32]
//   GEMM3: [16x32]x[32x80]   (78 tri outputs padded to 80)
// Epilogues: elu / elu / softplus; then L gather via per-warp smem scratch,
// LL^T with 2 lanes per sample (6 rows each), direct float4 stores.

#define TPB 128
#define NIN 12

typedef unsigned int u32;
typedef unsigned short u16;

// ---- smem layout (bytes) ----
#define O_W1H 0          // 128 rows x 48B   (16 bf16 used: 12 wts, b1@12, zeros)
#define O_W1L 6144
#define O_W2H 12288      // 32 rows x 272B   (128 bf16 used)
#define O_W2L 20992
#define O_W3H 29696      // 80 rows x 80B    (32 bf16 used; rows 78,79 zero)
#define O_W3L 36096
#define O_B2  42496      // 32 f32
#define O_B3  42624      // 80 f32 (padded)
#define O_SCR 42944      // 4 warps x 16 samples x 84 f32
#define SMEM_BYTES (O_SCR + 4 * 16 * 84 * 4)   // 64448

__device__ __forceinline__ u32 pack_bf16x2(float e0, float e1) {  // e0 -> low half
    u32 d;
    asm("cvt.rn.bf16x2.f32 %0, %1, %2;" : "=r"(d) : "f"(e1), "f"(e0));
    return d;
}
__device__ __forceinline__ void split2(float f0, float f1, u32& hi, u32& lo) {
    hi = pack_bf16x2(f0, f1);
    float h0 = __uint_as_float(hi << 16);
    float h1 = __uint_as_float(hi & 0xffff0000u);
    lo = pack_bf16x2(f0 - h0, f1 - h1);
}
__device__ __forceinline__ void split1(float f, u16& h, u16& l) {
    __nv_bfloat16 bh = __float2bfloat16(f);
    float fh = __bfloat162float(bh);
    h = __bfloat16_as_ushort(bh);
    l = __bfloat16_as_ushort(__float2bfloat16(f - fh));
}
__device__ __forceinline__ float elu_f(float p)  { return p > 0.f ? p : (__expf(p) - 1.f); }
__device__ __forceinline__ float softp(float t)  { return fmaxf(t, 0.f) + log1pf(__expf(-fabsf(t))); }

__device__ __forceinline__ void mma16816(float* d, u32 a0, u32 a1, u32 a2, u32 a3,
                                         u32 b0, u32 b1) {
    asm volatile(
        "mma.sync.aligned.m16n8k16.row.col.f32.bf16.bf16.f32 "
        "{%0,%1,%2,%3},{%4,%5,%6,%7},{%8,%9},{%0,%1,%2,%3};"
        : "+f"(d[0]), "+f"(d[1]), "+f"(d[2]), "+f"(d[3])
        : "r"(a0), "r"(a1), "r"(a2), "r"(a3), "r"(b0), "r"(b1));
}

__global__ void __launch_bounds__(TPB, 3)
qnc_mma_kernel(const float* __restrict__ x,
               const float* __restrict__ W1, const float* __restrict__ b1,
               const float* __restrict__ W2, const float* __restrict__ b2,
               const float* __restrict__ W3, const float* __restrict__ b3,
               float* __restrict__ out)
{
    extern __shared__ char sm[];
    float* smf = reinterpret_cast<float*>(sm);
    const int tid  = threadIdx.x;
    const int lane = tid & 31;
    const int w    = tid >> 5;
    const int g    = lane >> 2;     // 0..7  (fragment row group)
    const int tq   = lane & 3;      // 0..3  (fragment col group)

    // ---- zero weight region (covers all padding) ----
    for (int i = tid; i < O_SCR / 4; i += TPB)
        reinterpret_cast<u32*>(sm)[i] = 0u;
    __syncthreads();

    // ---- stage weights (bf16 hi/lo) ----
    for (int i = tid; i < 128 * NIN; i += TPB) {          // W1 [128][12]
        int n = i / NIN, k = i - n * NIN;
        u16 h, l;
        split1(W1[i], h, l);
        reinterpret_cast<u16*>(sm + O_W1H)[n * 24 + k] = h;
        reinterpret_cast<u16*>(sm + O_W1L)[n * 24 + k] = l;
    }
    for (int n = tid; n < 128; n += TPB) {                // b1 as K-col 12
        u16 h, l;
        split1(b1[n], h, l);
        reinterpret_cast<u16*>(sm + O_W1H)[n * 24 + 12] = h;
        reinterpret_cast<u16*>(sm + O_W1L)[n * 24 + 12] = l;
    }
    for (int i = tid; i < 32 * 128; i += TPB) {           // W2 [32][128]
        int n = i >> 7, k = i & 127;
        u16 h, l;
        split1(W2[i], h, l);
        reinterpret_cast<u16*>(sm + O_W2H)[n * 136 + k] = h;
        reinterpret_cast<u16*>(sm + O_W2L)[n * 136 + k] = l;
    }
    for (int i = tid; i < 78 * 32; i += TPB) {            // W3 [78][32]
        int n = i >> 5, k = i & 31;
        u16 h, l;
        split1(W3[i], h, l);
        reinterpret_cast<u16*>(sm + O_W3H)[n * 40 + k] = h;
        reinterpret_cast<u16*>(sm + O_W3L)[n * 40 + k] = l;
    }
    for (int i = tid; i < 32; i += TPB) smf[O_B2 / 4 + i] = b2[i];
    for (int i = tid; i < 78; i += TPB) smf[O_B3 / 4 + i] = b3[i];
    __syncthreads();

    // ---- A1 fragments from x (rows g and g+8 of this warp's 16-sample tile) ----
    const int warp_s0 = blockIdx.x * 64 + w * 16;
    const float* xr  = x + (size_t)(warp_s0 + g) * NIN;
    const float* xr8 = xr + 8 * NIN;
    float2 xa = *reinterpret_cast<const float2*>(xr  + 2 * tq);     // cols 2t,2t+1
    float2 xb = *reinterpret_cast<const float2*>(xr8 + 2 * tq);
    float2 xc, xd;                                                   // cols 8+2t,9+2t
    if (tq < 2) {
        xc = *reinterpret_cast<const float2*>(xr  + 8 + 2 * tq);
        xd = *reinterpret_cast<const float2*>(xr8 + 8 + 2 * tq);
    } else {
        float one = (tq == 2) ? 1.f : 0.f;                           // bias col 12
        xc = make_float2(one, 0.f);
        xd = make_float2(one, 0.f);
    }
    u32 a1h[4], a1l[4];
    split2(xa.x, xa.y, a1h[0], a1l[0]);
    split2(xb.x, xb.y, a1h[1], a1l[1]);
    split2(xc.x, xc.y, a1h[2], a1l[2]);
    split2(xd.x, xd.y, a1h[3], a1l[3]);

    // ---- GEMM1: D1[16x128], 16 n-tiles ----
    float acc1[16][4];
#pragma unroll
    for (int j = 0; j < 16; j++) acc1[j][0] = acc1[j][1] = acc1[j][2] = acc1[j][3] = 0.f;
#pragma unroll
    for (int j = 0; j < 16; j++) {
        const char* ph = sm + O_W1H + (8 * j + g) * 48 + 4 * tq;
        const char* pl = sm + O_W1L + (8 * j + g) * 48 + 4 * tq;
        u32 bh0 = *reinterpret_cast<const u32*>(ph);
        u32 bh1 = *reinterpret_cast<const u32*>(ph + 16);
        u32 bl0 = *reinterpret_cast<const u32*>(pl);
        u32 bl1 = *reinterpret_cast<const u32*>(pl + 16);
        mma16816(acc1[j], a1h[0], a1h[1], a1h[2], a1h[3], bh0, bh1);
        mma16816(acc1[j], a1h[0], a1h[1], a1h[2], a1h[3], bl0, bl1);
        mma16816(acc1[j], a1l[0], a1l[1], a1l[2], a1l[3], bh0, bh1);
    }

    // ---- epi1: elu -> A2 fragments (pure in-register repack) ----
    u32 a2h[8][4], a2l[8][4];
#pragma unroll
    for (int s = 0; s < 8; s++) {
        float e00 = elu_f(acc1[2 * s][0]),     e01 = elu_f(acc1[2 * s][1]);
        float e02 = elu_f(acc1[2 * s][2]),     e03 = elu_f(acc1[2 * s][3]);
        float e10 = elu_f(acc1[2 * s + 1][0]), e11 = elu_f(acc1[2 * s + 1][1]);
        float e12 = elu_f(acc1[2 * s + 1][2]), e13 = elu_f(acc1[2 * s + 1][3]);
        split2(e00, e01, a2h[s][0], a2l[s][0]);
        split2(e02, e03, a2h[s][1], a2l[s][1]);
        split2(e10, e11, a2h[s][2], a2l[s][2]);
        split2(e12, e13, a2h[s][3], a2l[s][3]);
    }

    // ---- GEMM2: D2[16x32], 8 k-steps x 4 n-tiles ----
    float acc2[4][4];
#pragma unroll
    for (int j = 0; j < 4; j++) acc2[j][0] = acc2[j][1] = acc2[j][2] = acc2[j][3] = 0.f;
#pragma unroll
    for (int s = 0; s < 8; s++) {
#pragma unroll
        for (int j = 0; j < 4; j++) {
            const char* ph = sm + O_W2H + (8 * j + g) * 272 + 32 * s + 4 * tq;
            const char* pl = sm + O_W2L + (8 * j + g) * 272 + 32 * s + 4 * tq;
            u32 bh0 = *reinterpret_cast<const u32*>(ph);
            u32 bh1 = *reinterpret_cast<const u32*>(ph + 16);
            u32 bl0 = *reinterpret_cast<const u32*>(pl);
            u32 bl1 = *reinterpret_cast<const u32*>(pl + 16);
            mma16816(acc2[j], a2h[s][0], a2h[s][1], a2h[s][2], a2h[s][3], bh0, bh1);
            mma16816(acc2[j], a2h[s][0], a2h[s][1], a2h[s][2], a2h[s][3], bl0, bl1);
            mma16816(acc2[j], a2l[s][0], a2l[s][1], a2l[s][2], a2l[s][3], bh0, bh1);
        }
    }

    // ---- epi2: +b2, elu -> A3 fragments ----
    float h2e[16];
#pragma unroll
    for (int j = 0; j < 4; j++) {
        float2 bb = *reinterpret_cast<const float2*>(smf + O_B2 / 4 + 8 * j + 2 * tq);
        h2e[4 * j + 0] = elu_f(acc2[j][0] + bb.x);
        h2e[4 * j + 1] = elu_f(acc2[j][1] + bb.y);
        h2e[4 * j + 2] = elu_f(acc2[j][2] + bb.x);
        h2e[4 * j + 3] = elu_f(acc2[j][3] + bb.y);
    }
    u32 a3h[2][4], a3l[2][4];
#pragma unroll
    for (int s = 0; s < 2; s++) {
        split2(h2e[8 * s + 0], h2e[8 * s + 1], a3h[s][0], a3l[s][0]);
        split2(h2e[8 * s + 2], h2e[8 * s + 3], a3h[s][1], a3l[s][1]);
        split2(h2e[8 * s + 4], h2e[8 * s + 5], a3h[s][2], a3l[s][2]);
        split2(h2e[8 * s + 6], h2e[8 * s + 7], a3h[s][3], a3l[s][3]);
    }

    // ---- GEMM3: D3[16x80], 2 k-steps x 10 n-tiles ----
    float acc3[10][4];
#pragma unroll
    for (int j = 0; j < 10; j++) acc3[j][0] = acc3[j][1] = acc3[j][2] = acc3[j][3] = 0.f;
#pragma unroll
    for (int s = 0; s < 2; s++) {
#pragma unroll
        for (int j = 0; j < 10; j++) {
            const char* ph = sm + O_W3H + (8 * j + g) * 80 + 32 * s + 4 * tq;
            const char* pl = sm + O_W3L + (8 * j + g) * 80 + 32 * s + 4 * tq;
            u32 bh0 = *reinterpret_cast<const u32*>(ph);
            u32 bh1 = *reinterpret_cast<const u32*>(ph + 16);
            u32 bl0 = *reinterpret_cast<const u32*>(pl);
            u32 bl1 = *reinterpret_cast<const u32*>(pl + 16);
            mma16816(acc3[j], a3h[s][0], a3h[s][1], a3h[s][2], a3h[s][3], bh0, bh1);
            mma16816(acc3[j], a3h[s][0], a3h[s][1], a3h[s][2], a3h[s][3], bl0, bl1);
            mma16816(acc3[j], a3l[s][0], a3l[s][1], a3l[s][2], a3l[s][3], bh0, bh1);
        }
    }

    // ---- epi3: +b3, softplus -> scatter L rows into per-warp smem scratch ----
    float* scr = smf + O_SCR / 4 + w * 16 * 84;
#pragma unroll
    for (int j = 0; j < 10; j++) {
        int col = 8 * j + 2 * tq;
        float2 bb = *reinterpret_cast<const float2*>(smf + O_B3 / 4 + col);
        float v0 = softp(acc3[j][0] + bb.x);
        float v1 = softp(acc3[j][1] + bb.y);
        float v2 = softp(acc3[j][2] + bb.x);
        float v3 = softp(acc3[j][3] + bb.y);
        *reinterpret_cast<float2*>(scr + g * 84 + col)       = make_float2(v0, v1);
        *reinterpret_cast<float2*>(scr + (g + 8) * 84 + col) = make_float2(v2, v3);
    }
    __syncwarp();

    // ---- gather full L row (2 lanes per sample), LL^T, direct stores ----
    const int s   = lane & 15;
    const int r0  = (lane >> 4) * 6;
    const float* Ls = scr + s * 84;
    float Lr[78];
#pragma unroll
    for (int i = 0; i < 39; i++) {
        float2 t = *reinterpret_cast<const float2*>(Ls + 2 * i);
        Lr[2 * i] = t.x;
        Lr[2 * i + 1] = t.y;
    }
    float4* ob = reinterpret_cast<float4*>(out + (size_t)(warp_s0 + s) * 144);
#pragma unroll
    for (int rr = 0; rr < 6; rr++) {
        const int r = r0 + rr;
        float row[12];
#pragma unroll
        for (int c = 0; c < 12; c++) {
            const int mn = (r < c) ? r : c;
            const int ro = r * (r + 1) / 2, co = c * (c + 1) / 2;
            float acc = Lr[ro] * Lr[co];
#pragma unroll
            for (int jj = 1; jj <= mn; jj++) acc = fmaf(Lr[ro + jj], Lr[co + jj], acc);
            row[c] = acc;
        }
#pragma unroll
        for (int c4 = 0; c4 < 3; c4++)
            ob[r * 3 + c4] = make_float4(row[4 * c4], row[4 * c4 + 1],
                                         row[4 * c4 + 2], row[4 * c4 + 3]);
    }
}

extern "C" void kernel_launch(void* const* d_in, const int* in_sizes, int n_in,
                              void* d_out, int out_size)
{
    const float* x  = (const float*)d_in[0];
    const float* W1 = (const float*)d_in[1];
    const float* b1 = (const float*)d_in[2];
    const float* W2 = (const float*)d_in[3];
    const float* b2 = (const float*)d_in[4];
    const float* W3 = (const float*)d_in[5];
    const float* b3 = (const float*)d_in[6];

    const int B = in_sizes[0] / NIN;            // 262144
    const int grid = B / 64;                    // 4096 CTAs (64 samples each)

    cudaFuncSetAttribute(qnc_mma_kernel, cudaFuncAttributeMaxDynamicSharedMemorySize, SMEM_BYTES);
    qnc_mma_kernel<<<grid, TPB, SMEM_BYTES>>>(x, W1, b1, W2, b2, W3, b3, (float*)d_out);
}

// round 4
// speedup vs baseline: 1.4235x; 1.1285x over previous
#include <cuda_runtime.h>
#include <cuda_bf16.h>
#include <cstdint>

// QuadraticNetCholesky via warp-level mma.sync (HMMA, bf16x3 split) on sm_103.
// R4: fragment-order weight staging (1 LDS.128 per mma tile per lane) and
// 4 CTAs/SM (smem trimmed to ~56KB).
// Per warp: 16 samples. D-fragment of layer k == A-fragment of layer k+1.
//   GEMM1: [16x16]x[16x128]  (K=12 + bias col + pad), tiles 0..15
//   GEMM2: [16x128]x[128x32], tiles 16..47  (t = 16 + 4s + j)
//   GEMM3: [16x32]x[32x80],   tiles 48..67  (t = 48 + 10s + j)

#define TPB 128
#define NIN 12
#define NTILE 68

typedef unsigned int u32;
typedef unsigned short u16;

// ---- smem layout (bytes) ----
#define O_FRAG 0                       // 68 tiles x 32 lanes x 16B = 34816
#define O_B2   34816                   // 32 f32
#define O_B3   34944                   // 80 f32 (padded)
#define O_SCR  35264                   // 4 warps x 16 samples x 84 f32 = 21504
#define SMEM_BYTES (O_SCR + 4 * 16 * 84 * 4)    // 56768 -> 56KB pages, 4 CTAs/SM

__device__ __forceinline__ u32 pack_bf16x2(float e0, float e1) {  // e0 -> low half
    u32 d;
    asm("cvt.rn.bf16x2.f32 %0, %1, %2;" : "=r"(d) : "f"(e1), "f"(e0));
    return d;
}
__device__ __forceinline__ void split2(float f0, float f1, u32& hi, u32& lo) {
    hi = pack_bf16x2(f0, f1);
    float h0 = __uint_as_float(hi << 16);
    float h1 = __uint_as_float(hi & 0xffff0000u);
    lo = pack_bf16x2(f0 - h0, f1 - h1);
}
__device__ __forceinline__ float elu_f(float p)  { return p > 0.f ? p : (__expf(p) - 1.f); }
__device__ __forceinline__ float softp(float t)  { return fmaxf(t, 0.f) + log1pf(__expf(-fabsf(t))); }

__device__ __forceinline__ void mma16816(float* d, u32 a0, u32 a1, u32 a2, u32 a3,
                                         u32 b0, u32 b1) {
    asm volatile(
        "mma.sync.aligned.m16n8k16.row.col.f32.bf16.bf16.f32 "
        "{%0,%1,%2,%3},{%4,%5,%6,%7},{%8,%9},{%0,%1,%2,%3};"
        : "+f"(d[0]), "+f"(d[1]), "+f"(d[2]), "+f"(d[3])
        : "r"(a0), "r"(a1), "r"(a2), "r"(a3), "r"(b0), "r"(b1));
}
// 3-product split accumulate: D += A*B with A=(ah,al), B=(f.x,f.y | f.z,f.w)
__device__ __forceinline__ void mma3(float* d, const u32* ah, const u32* al, uint4 f) {
    mma16816(d, ah[0], ah[1], ah[2], ah[3], f.x, f.y);   // hi*hi
    mma16816(d, ah[0], ah[1], ah[2], ah[3], f.z, f.w);   // hi*lo
    mma16816(d, al[0], al[1], al[2], al[3], f.x, f.y);   // lo*hi
}

__global__ void __launch_bounds__(TPB, 4)
qnc_mma_kernel(const float* __restrict__ x,
               const float* __restrict__ W1, const float* __restrict__ b1,
               const float* __restrict__ W2, const float* __restrict__ b2,
               const float* __restrict__ W3, const float* __restrict__ b3,
               float* __restrict__ out)
{
    extern __shared__ char sm[];
    float* smf = reinterpret_cast<float*>(sm);
    const int tid  = threadIdx.x;
    const int lane = tid & 31;
    const int w    = tid >> 5;
    const int g    = lane >> 2;     // fragment row group 0..7
    const int tq   = lane & 3;      // fragment col group 0..3

    // ---- stage weights in fragment order: entry (t, lane) -> 16B uint4 ----
    // lane (g2,tq2) of tile t holds B cols n=8j+g2, k = {2tq2,2tq2+1} (b0)
    // and {8+2tq2, 9+2tq2} (b1), packed hi then lo.
    for (int idx = tid; idx < NTILE * 32; idx += TPB) {
        const int t  = idx >> 5;
        const int l2 = idx & 31;
        const int g2 = l2 >> 2, tq2 = l2 & 3;
        float v0, v1, v2, v3;
        if (t < 16) {                         // GEMM1: W1[128][12] + b1 col 12
            const int n = 8 * t + g2;
            const float* r = W1 + n * NIN;
            v0 = r[2 * tq2]; v1 = r[2 * tq2 + 1];
            const int k2 = 8 + 2 * tq2;
            v2 = (k2 < NIN) ? r[k2] : ((k2 == 12) ? b1[n] : 0.f);
            v3 = (k2 + 1 < NIN) ? r[k2 + 1] : ((k2 + 1 == 12) ? b1[n] : 0.f);
        } else if (t < 48) {                  // GEMM2: W2[32][128]
            const int tt = t - 16, s = tt >> 2, j = tt & 3;
            const float* r = W2 + (8 * j + g2) * 128 + 16 * s;
            v0 = r[2 * tq2]; v1 = r[2 * tq2 + 1];
            v2 = r[8 + 2 * tq2]; v3 = r[9 + 2 * tq2];
        } else {                              // GEMM3: W3[78][32], rows 78,79 = 0
            const int tt = t - 48, s = tt / 10, j = tt - 10 * s;
            const int n = 8 * j + g2;
            if (n < 78) {
                const float* r = W3 + n * 32 + 16 * s;
                v0 = r[2 * tq2]; v1 = r[2 * tq2 + 1];
                v2 = r[8 + 2 * tq2]; v3 = r[9 + 2 * tq2];
            } else {
                v0 = v1 = v2 = v3 = 0.f;
            }
        }
        u32 h0, l0, h1, l1;
        split2(v0, v1, h0, l0);
        split2(v2, v3, h1, l1);
        *reinterpret_cast<uint4*>(sm + O_FRAG + t * 512 + l2 * 16) =
            make_uint4(h0, h1, l0, l1);
    }
    for (int i = tid; i < 32; i += TPB) smf[O_B2 / 4 + i] = b2[i];
    for (int i = tid; i < 80; i += TPB) smf[O_B3 / 4 + i] = (i < 78) ? b3[i] : 0.f;
    __syncthreads();

    const uint4* frag = reinterpret_cast<const uint4*>(sm + O_FRAG) + lane;  // stride 32/tile

    // ---- A1 fragments from x (rows g, g+8 of this warp's 16-sample tile) ----
    const int warp_s0 = blockIdx.x * 64 + w * 16;
    const float* xr  = x + (size_t)(warp_s0 + g) * NIN;
    const float* xr8 = xr + 8 * NIN;
    float2 xa = *reinterpret_cast<const float2*>(xr  + 2 * tq);
    float2 xb = *reinterpret_cast<const float2*>(xr8 + 2 * tq);
    float2 xc, xd;
    if (tq < 2) {
        xc = *reinterpret_cast<const float2*>(xr  + 8 + 2 * tq);
        xd = *reinterpret_cast<const float2*>(xr8 + 8 + 2 * tq);
    } else {
        float one = (tq == 2) ? 1.f : 0.f;    // bias col 12
        xc = make_float2(one, 0.f);
        xd = make_float2(one, 0.f);
    }
    u32 a1h[4], a1l[4];
    split2(xa.x, xa.y, a1h[0], a1l[0]);
    split2(xb.x, xb.y, a1h[1], a1l[1]);
    split2(xc.x, xc.y, a1h[2], a1l[2]);
    split2(xd.x, xd.y, a1h[3], a1l[3]);

    // ---- GEMM1: D1[16x128], 16 independent tiles ----
    float acc1[16][4];
#pragma unroll
    for (int j = 0; j < 16; j++) acc1[j][0] = acc1[j][1] = acc1[j][2] = acc1[j][3] = 0.f;
#pragma unroll
    for (int j = 0; j < 16; j++)
        mma3(acc1[j], a1h, a1l, frag[j * 32]);

    // ---- epi1: elu -> A2 fragments (in-register repack) ----
    u32 a2h[8][4], a2l[8][4];
#pragma unroll
    for (int s = 0; s < 8; s++) {
        float e00 = elu_f(acc1[2 * s][0]),     e01 = elu_f(acc1[2 * s][1]);
        float e02 = elu_f(acc1[2 * s][2]),     e03 = elu_f(acc1[2 * s][3]);
        float e10 = elu_f(acc1[2 * s + 1][0]), e11 = elu_f(acc1[2 * s + 1][1]);
        float e12 = elu_f(acc1[2 * s + 1][2]), e13 = elu_f(acc1[2 * s + 1][3]);
        split2(e00, e01, a2h[s][0], a2l[s][0]);
        split2(e02, e03, a2h[s][1], a2l[s][1]);
        split2(e10, e11, a2h[s][2], a2l[s][2]);
        split2(e12, e13, a2h[s][3], a2l[s][3]);
    }

    // ---- GEMM2: D2[16x32], 8 k-steps x 4 n-tiles ----
    float acc2[4][4];
#pragma unroll
    for (int j = 0; j < 4; j++) acc2[j][0] = acc2[j][1] = acc2[j][2] = acc2[j][3] = 0.f;
#pragma unroll
    for (int s = 0; s < 8; s++)
#pragma unroll
        for (int j = 0; j < 4; j++)
            mma3(acc2[j], a2h[s], a2l[s], frag[(16 + 4 * s + j) * 32]);

    // ---- epi2: +b2, elu -> A3 fragments ----
    float h2e[16];
#pragma unroll
    for (int j = 0; j < 4; j++) {
        float2 bb = *reinterpret_cast<const float2*>(smf + O_B2 / 4 + 8 * j + 2 * tq);
        h2e[4 * j + 0] = elu_f(acc2[j][0] + bb.x);
        h2e[4 * j + 1] = elu_f(acc2[j][1] + bb.y);
        h2e[4 * j + 2] = elu_f(acc2[j][2] + bb.x);
        h2e[4 * j + 3] = elu_f(acc2[j][3] + bb.y);
    }
    u32 a3h[2][4], a3l[2][4];
#pragma unroll
    for (int s = 0; s < 2; s++) {
        split2(h2e[8 * s + 0], h2e[8 * s + 1], a3h[s][0], a3l[s][0]);
        split2(h2e[8 * s + 2], h2e[8 * s + 3], a3h[s][1], a3l[s][1]);
        split2(h2e[8 * s + 4], h2e[8 * s + 5], a3h[s][2], a3l[s][2]);
        split2(h2e[8 * s + 6], h2e[8 * s + 7], a3h[s][3], a3l[s][3]);
    }

    // ---- GEMM3: D3[16x80], 2 k-steps x 10 n-tiles ----
    float acc3[10][4];
#pragma unroll
    for (int j = 0; j < 10; j++) acc3[j][0] = acc3[j][1] = acc3[j][2] = acc3[j][3] = 0.f;
#pragma unroll
    for (int s = 0; s < 2; s++)
#pragma unroll
        for (int j = 0; j < 10; j++)
            mma3(acc3[j], a3h[s], a3l[s], frag[(48 + 10 * s + j) * 32]);

    // ---- epi3: +b3, softplus -> per-warp smem scratch (sample-major) ----
    float* scr = smf + O_SCR / 4 + w * 16 * 84;
#pragma unroll
    for (int j = 0; j < 10; j++) {
        int col = 8 * j + 2 * tq;
        float2 bb = *reinterpret_cast<const float2*>(smf + O_B3 / 4 + col);
        float v0 = softp(acc3[j][0] + bb.x);
        float v1 = softp(acc3[j][1] + bb.y);
        float v2 = softp(acc3[j][2] + bb.x);
        float v3 = softp(acc3[j][3] + bb.y);
        *reinterpret_cast<float2*>(scr + g * 84 + col)       = make_float2(v0, v1);
        *reinterpret_cast<float2*>(scr + (g + 8) * 84 + col) = make_float2(v2, v3);
    }
    __syncwarp();

    // ---- gather L (2 lanes/sample), LL^T, direct float4 stores ----
    const int s   = lane & 15;
    const int r0  = (lane >> 4) * 6;
    const float* Ls = scr + s * 84;
    float Lr[78];
#pragma unroll
    for (int i = 0; i < 19; i++) {
        float4 t4 = *reinterpret_cast<const float4*>(Ls + 4 * i);
        Lr[4 * i] = t4.x; Lr[4 * i + 1] = t4.y; Lr[4 * i + 2] = t4.z; Lr[4 * i + 3] = t4.w;
    }
    {
        float2 t2 = *reinterpret_cast<const float2*>(Ls + 76);
        Lr[76] = t2.x; Lr[77] = t2.y;
    }
    float4* ob = reinterpret_cast<float4*>(out + (size_t)(warp_s0 + s) * 144);
#pragma unroll
    for (int rr = 0; rr < 6; rr++) {
        const int r = r0 + rr;
        float row[12];
#pragma unroll
        for (int c = 0; c < 12; c++) {
            const int mn = (r < c) ? r : c;
            const int ro = r * (r + 1) / 2, co = c * (c + 1) / 2;
            float acc = Lr[ro] * Lr[co];
#pragma unroll
            for (int jj = 1; jj <= mn; jj++) acc = fmaf(Lr[ro + jj], Lr[co + jj], acc);
            row[c] = acc;
        }
#pragma unroll
        for (int c4 = 0; c4 < 3; c4++)
            ob[r * 3 + c4] = make_float4(row[4 * c4], row[4 * c4 + 1],
                                         row[4 * c4 + 2], row[4 * c4 + 3]);
    }
}

extern "C" void kernel_launch(void* const* d_in, const int* in_sizes, int n_in,
                              void* d_out, int out_size)
{
    const float* x  = (const float*)d_in[0];
    const float* W1 = (const float*)d_in[1];
    const float* b1 = (const float*)d_in[2];
    const float* W2 = (const float*)d_in[3];
    const float* b2 = (const float*)d_in[4];
    const float* W3 = (const float*)d_in[5];
    const float* b3 = (const float*)d_in[6];

    const int B = in_sizes[0] / NIN;            // 262144
    const int grid = B / 64;                    // 4096 CTAs (64 samples each)

    cudaFuncSetAttribute(qnc_mma_kernel, cudaFuncAttributeMaxDynamicSharedMemorySize, SMEM_BYTES);
    qnc_mma_kernel<<<grid, TPB, SMEM_BYTES>>>(x, W1, b1, W2, b2, W3, b3, (float*)d_out);
}

// round 5
// speedup vs baseline: 1.4974x; 1.0519x over previous
#include <cuda_runtime.h>
#include <cuda_bf16.h>
#include <cstdint>

// QuadraticNetCholesky via warp-level mma.sync (HMMA, bf16x3 split) on sm_103.
// R5: persistent CTAs (weights staged once per CTA, loop over sample tiles)
//     + fast softplus (__logf/__expf instead of log1pf).
// Per warp-job: 16 samples. D-fragment of layer k == A-fragment of layer k+1.
//   GEMM1: [16x16]x[16x128]  (K=12 + bias col + pad), tiles 0..15
//   GEMM2: [16x128]x[128x32], tiles 16..47  (t = 16 + 4s + j)
//   GEMM3: [16x32]x[32x80],   tiles 48..67  (t = 48 + 10s + j)

#define TPB 128
#define NIN 12
#define NTILE 68

typedef unsigned int u32;
typedef unsigned short u16;

// ---- smem layout (bytes) ----
#define O_FRAG 0                       // 68 tiles x 32 lanes x 16B = 34816
#define O_B2   34816                   // 32 f32
#define O_B3   34944                   // 80 f32 (padded)
#define O_SCR  35264                   // 4 warps x 16 samples x 84 f32 = 21504
#define SMEM_BYTES (O_SCR + 4 * 16 * 84 * 4)    // 56768 -> 4 CTAs/SM

__device__ __forceinline__ u32 pack_bf16x2(float e0, float e1) {  // e0 -> low half
    u32 d;
    asm("cvt.rn.bf16x2.f32 %0, %1, %2;" : "=r"(d) : "f"(e1), "f"(e0));
    return d;
}
__device__ __forceinline__ void split2(float f0, float f1, u32& hi, u32& lo) {
    hi = pack_bf16x2(f0, f1);
    float h0 = __uint_as_float(hi << 16);
    float h1 = __uint_as_float(hi & 0xffff0000u);
    lo = pack_bf16x2(f0 - h0, f1 - h1);
}
__device__ __forceinline__ float elu_f(float p) { return p > 0.f ? p : (__expf(p) - 1.f); }
// fast softplus: max(x,0) + log(1 + exp(-|x|)); abs err ~1e-7, outputs O(1)
__device__ __forceinline__ float softp(float t) {
    return fmaxf(t, 0.f) + __logf(1.f + __expf(-fabsf(t)));
}

__device__ __forceinline__ void mma16816(float* d, u32 a0, u32 a1, u32 a2, u32 a3,
                                         u32 b0, u32 b1) {
    asm volatile(
        "mma.sync.aligned.m16n8k16.row.col.f32.bf16.bf16.f32 "
        "{%0,%1,%2,%3},{%4,%5,%6,%7},{%8,%9},{%0,%1,%2,%3};"
        : "+f"(d[0]), "+f"(d[1]), "+f"(d[2]), "+f"(d[3])
        : "r"(a0), "r"(a1), "r"(a2), "r"(a3), "r"(b0), "r"(b1));
}
// 3-product split accumulate: D += A*B with A=(ah,al), B=(f.x,f.y | f.z,f.w)
__device__ __forceinline__ void mma3(float* d, const u32* ah, const u32* al, uint4 f) {
    mma16816(d, ah[0], ah[1], ah[2], ah[3], f.x, f.y);   // hi*hi
    mma16816(d, ah[0], ah[1], ah[2], ah[3], f.z, f.w);   // hi*lo
    mma16816(d, al[0], al[1], al[2], al[3], f.x, f.y);   // lo*hi
}

__global__ void __launch_bounds__(TPB, 4)
qnc_mma_kernel(const float* __restrict__ x,
               const float* __restrict__ W1, const float* __restrict__ b1,
               const float* __restrict__ W2, const float* __restrict__ b2,
               const float* __restrict__ W3, const float* __restrict__ b3,
               float* __restrict__ out, int ntiles)
{
    extern __shared__ char sm[];
    float* smf = reinterpret_cast<float*>(sm);
    const int tid  = threadIdx.x;
    const int lane = tid & 31;
    const int w    = tid >> 5;
    const int g    = lane >> 2;     // fragment row group 0..7
    const int tq   = lane & 3;      // fragment col group 0..3

    // ---- stage weights ONCE per CTA in fragment order ----
    for (int idx = tid; idx < NTILE * 32; idx += TPB) {
        const int t  = idx >> 5;
        const int l2 = idx & 31;
        const int g2 = l2 >> 2, tq2 = l2 & 3;
        float v0, v1, v2, v3;
        if (t < 16) {                         // GEMM1: W1[128][12] + b1 col 12
            const int n = 8 * t + g2;
            const float* r = W1 + n * NIN;
            v0 = r[2 * tq2]; v1 = r[2 * tq2 + 1];
            const int k2 = 8 + 2 * tq2;
            v2 = (k2 < NIN) ? r[k2] : ((k2 == 12) ? b1[n] : 0.f);
            v3 = (k2 + 1 < NIN) ? r[k2 + 1] : ((k2 + 1 == 12) ? b1[n] : 0.f);
        } else if (t < 48) {                  // GEMM2: W2[32][128]
            const int tt = t - 16, s = tt >> 2, j = tt & 3;
            const float* r = W2 + (8 * j + g2) * 128 + 16 * s;
            v0 = r[2 * tq2]; v1 = r[2 * tq2 + 1];
            v2 = r[8 + 2 * tq2]; v3 = r[9 + 2 * tq2];
        } else {                              // GEMM3: W3[78][32], rows 78,79 = 0
            const int tt = t - 48, s = tt / 10, j = tt - 10 * s;
            const int n = 8 * j + g2;
            if (n < 78) {
                const float* r = W3 + n * 32 + 16 * s;
                v0 = r[2 * tq2]; v1 = r[2 * tq2 + 1];
                v2 = r[8 + 2 * tq2]; v3 = r[9 + 2 * tq2];
            } else {
                v0 = v1 = v2 = v3 = 0.f;
            }
        }
        u32 h0, l0, h1, l1;
        split2(v0, v1, h0, l0);
        split2(v2, v3, h1, l1);
        *reinterpret_cast<uint4*>(sm + O_FRAG + t * 512 + l2 * 16) =
            make_uint4(h0, h1, l0, l1);
    }
    for (int i = tid; i < 32; i += TPB) smf[O_B2 / 4 + i] = b2[i];
    for (int i = tid; i < 80; i += TPB) smf[O_B3 / 4 + i] = (i < 78) ? b3[i] : 0.f;
    __syncthreads();

    const uint4* frag = reinterpret_cast<const uint4*>(sm + O_FRAG) + lane;
    float* scr = smf + O_SCR / 4 + w * 16 * 84;

    // ---- persistent loop over 64-sample tiles ----
    for (int tile = blockIdx.x; tile < ntiles; tile += gridDim.x) {
        const int warp_s0 = tile * 64 + w * 16;

        // A1 fragments from x (rows g, g+8 of this warp's 16-sample tile)
        const float* xr  = x + (size_t)(warp_s0 + g) * NIN;
        const float* xr8 = xr + 8 * NIN;
        float2 xa = *reinterpret_cast<const float2*>(xr  + 2 * tq);
        float2 xb = *reinterpret_cast<const float2*>(xr8 + 2 * tq);
        float2 xc, xd;
        if (tq < 2) {
            xc = *reinterpret_cast<const float2*>(xr  + 8 + 2 * tq);
            xd = *reinterpret_cast<const float2*>(xr8 + 8 + 2 * tq);
        } else {
            float one = (tq == 2) ? 1.f : 0.f;    // bias col 12
            xc = make_float2(one, 0.f);
            xd = make_float2(one, 0.f);
        }
        u32 a1h[4], a1l[4];
        split2(xa.x, xa.y, a1h[0], a1l[0]);
        split2(xb.x, xb.y, a1h[1], a1l[1]);
        split2(xc.x, xc.y, a1h[2], a1l[2]);
        split2(xd.x, xd.y, a1h[3], a1l[3]);

        // GEMM1: D1[16x128], 16 independent tiles
        float acc1[16][4];
#pragma unroll
        for (int j = 0; j < 16; j++) acc1[j][0] = acc1[j][1] = acc1[j][2] = acc1[j][3] = 0.f;
#pragma unroll
        for (int j = 0; j < 16; j++)
            mma3(acc1[j], a1h, a1l, frag[j * 32]);

        // epi1: elu -> A2 fragments (in-register repack)
        u32 a2h[8][4], a2l[8][4];
#pragma unroll
        for (int s = 0; s < 8; s++) {
            float e00 = elu_f(acc1[2 * s][0]),     e01 = elu_f(acc1[2 * s][1]);
            float e02 = elu_f(acc1[2 * s][2]),     e03 = elu_f(acc1[2 * s][3]);
            float e10 = elu_f(acc1[2 * s + 1][0]), e11 = elu_f(acc1[2 * s + 1][1]);
            float e12 = elu_f(acc1[2 * s + 1][2]), e13 = elu_f(acc1[2 * s + 1][3]);
            split2(e00, e01, a2h[s][0], a2l[s][0]);
            split2(e02, e03, a2h[s][1], a2l[s][1]);
            split2(e10, e11, a2h[s][2], a2l[s][2]);
            split2(e12, e13, a2h[s][3], a2l[s][3]);
        }

        // GEMM2: D2[16x32], 8 k-steps x 4 n-tiles
        float acc2[4][4];
#pragma unroll
        for (int j = 0; j < 4; j++) acc2[j][0] = acc2[j][1] = acc2[j][2] = acc2[j][3] = 0.f;
#pragma unroll
        for (int s = 0; s < 8; s++)
#pragma unroll
            for (int j = 0; j < 4; j++)
                mma3(acc2[j], a2h[s], a2l[s], frag[(16 + 4 * s + j) * 32]);

        // epi2: +b2, elu -> A3 fragments
        float h2e[16];
#pragma unroll
        for (int j = 0; j < 4; j++) {
            float2 bb = *reinterpret_cast<const float2*>(smf + O_B2 / 4 + 8 * j + 2 * tq);
            h2e[4 * j + 0] = elu_f(acc2[j][0] + bb.x);
            h2e[4 * j + 1] = elu_f(acc2[j][1] + bb.y);
            h2e[4 * j + 2] = elu_f(acc2[j][2] + bb.x);
            h2e[4 * j + 3] = elu_f(acc2[j][3] + bb.y);
        }
        u32 a3h[2][4], a3l[2][4];
#pragma unroll
        for (int s = 0; s < 2; s++) {
            split2(h2e[8 * s + 0], h2e[8 * s + 1], a3h[s][0], a3l[s][0]);
            split2(h2e[8 * s + 2], h2e[8 * s + 3], a3h[s][1], a3l[s][1]);
            split2(h2e[8 * s + 4], h2e[8 * s + 5], a3h[s][2], a3l[s][2]);
            split2(h2e[8 * s + 6], h2e[8 * s + 7], a3h[s][3], a3l[s][3]);
        }

        // GEMM3: D3[16x80], 2 k-steps x 10 n-tiles
        float acc3[10][4];
#pragma unroll
        for (int j = 0; j < 10; j++) acc3[j][0] = acc3[j][1] = acc3[j][2] = acc3[j][3] = 0.f;
#pragma unroll
        for (int s = 0; s < 2; s++)
#pragma unroll
            for (int j = 0; j < 10; j++)
                mma3(acc3[j], a3h[s], a3l[s], frag[(48 + 10 * s + j) * 32]);

        // epi3: +b3, softplus -> per-warp smem scratch (sample-major)
        __syncwarp();                          // scratch reuse guard across loop iters
#pragma unroll
        for (int j = 0; j < 10; j++) {
            int col = 8 * j + 2 * tq;
            float2 bb = *reinterpret_cast<const float2*>(smf + O_B3 / 4 + col);
            float v0 = softp(acc3[j][0] + bb.x);
            float v1 = softp(acc3[j][1] + bb.y);
            float v2 = softp(acc3[j][2] + bb.x);
            float v3 = softp(acc3[j][3] + bb.y);
            *reinterpret_cast<float2*>(scr + g * 84 + col)       = make_float2(v0, v1);
            *reinterpret_cast<float2*>(scr + (g + 8) * 84 + col) = make_float2(v2, v3);
        }
        __syncwarp();

        // gather L (2 lanes/sample), LL^T, direct float4 stores
        const int s   = lane & 15;
        const int r0  = (lane >> 4) * 6;
        const float* Ls = scr + s * 84;
        float Lr[78];
#pragma unroll
        for (int i = 0; i < 19; i++) {
            float4 t4 = *reinterpret_cast<const float4*>(Ls + 4 * i);
            Lr[4 * i] = t4.x; Lr[4 * i + 1] = t4.y; Lr[4 * i + 2] = t4.z; Lr[4 * i + 3] = t4.w;
        }
        {
            float2 t2 = *reinterpret_cast<const float2*>(Ls + 76);
            Lr[76] = t2.x; Lr[77] = t2.y;
        }
        float4* ob = reinterpret_cast<float4*>(out + (size_t)(warp_s0 + s) * 144);
#pragma unroll
        for (int rr = 0; rr < 6; rr++) {
            const int r = r0 + rr;
            float row[12];
#pragma unroll
            for (int c = 0; c < 12; c++) {
                const int mn = (r < c) ? r : c;
                const int ro = r * (r + 1) / 2, co = c * (c + 1) / 2;
                float acc = Lr[ro] * Lr[co];
#pragma unroll
                for (int jj = 1; jj <= mn; jj++) acc = fmaf(Lr[ro + jj], Lr[co + jj], acc);
                row[c] = acc;
            }
#pragma unroll
            for (int c4 = 0; c4 < 3; c4++)
                ob[r * 3 + c4] = make_float4(row[4 * c4], row[4 * c4 + 1],
                                             row[4 * c4 + 2], row[4 * c4 + 3]);
        }
    }
}

extern "C" void kernel_launch(void* const* d_in, const int* in_sizes, int n_in,
                              void* d_out, int out_size)
{
    const float* x  = (const float*)d_in[0];
    const float* W1 = (const float*)d_in[1];
    const float* b1 = (const float*)d_in[2];
    const float* W2 = (const float*)d_in[3];
    const float* b2 = (const float*)d_in[4];
    const float* W3 = (const float*)d_in[5];
    const float* b3 = (const float*)d_in[6];

    const int B = in_sizes[0] / NIN;            // 262144
    const int ntiles = B / 64;                  // 4096
    const int grid = 592;                       // 4 CTAs x 148 SMs, persistent

    cudaFuncSetAttribute(qnc_mma_kernel, cudaFuncAttributeMaxDynamicSharedMemorySize, SMEM_BYTES);
    qnc_mma_kernel<<<grid, TPB, SMEM_BYTES>>>(x, W1, b1, W2, b2, W3, b3, (float*)d_out, ntiles);
}

// round 6
// speedup vs baseline: 2.0188x; 1.3483x over previous
#include <cuda_runtime.h>
#include <cuda_bf16.h>
#include <cstdint>

// QuadraticNetCholesky, R6: two kernels.
//  A: MLP via mma.sync bf16x3, fused per-k-step to minimize live regs
//     (24 warps/SM), writes L (softplus out, 78+2 floats) into out[s*144+0..79].
//  B: reads L from out, computes M = L L^T, overwrites out[s*144+0..143].

#define NIN 12
#define NTILE 68

typedef unsigned int u32;

// ---- kernel A smem (bytes) ----
#define O_FRAG 0                       // 68 tiles x 32 lanes x 16B = 34816
#define O_B2   34816                   // 32 f32
#define O_B3   34944                   // 80 f32
#define SMEM_A (34944 + 320)           // 35264

__device__ __forceinline__ u32 pack_bf16x2(float e0, float e1) {  // e0 -> low half
    u32 d;
    asm("cvt.rn.bf16x2.f32 %0, %1, %2;" : "=r"(d) : "f"(e1), "f"(e0));
    return d;
}
__device__ __forceinline__ void split2(float f0, float f1, u32& hi, u32& lo) {
    hi = pack_bf16x2(f0, f1);
    float h0 = __uint_as_float(hi << 16);
    float h1 = __uint_as_float(hi & 0xffff0000u);
    lo = pack_bf16x2(f0 - h0, f1 - h1);
}
__device__ __forceinline__ float elu_f(float p) { return p > 0.f ? p : (__expf(p) - 1.f); }
__device__ __forceinline__ float softp(float t) {
    return fmaxf(t, 0.f) + __logf(1.f + __expf(-fabsf(t)));
}

__device__ __forceinline__ void mma16816(float* d, u32 a0, u32 a1, u32 a2, u32 a3,
                                         u32 b0, u32 b1) {
    asm volatile(
        "mma.sync.aligned.m16n8k16.row.col.f32.bf16.bf16.f32 "
        "{%0,%1,%2,%3},{%4,%5,%6,%7},{%8,%9},{%0,%1,%2,%3};"
        : "+f"(d[0]), "+f"(d[1]), "+f"(d[2]), "+f"(d[3])
        : "r"(a0), "r"(a1), "r"(a2), "r"(a3), "r"(b0), "r"(b1));
}
__device__ __forceinline__ void mma3(float* d, const u32* ah, const u32* al, uint4 f) {
    mma16816(d, ah[0], ah[1], ah[2], ah[3], f.x, f.y);   // hi*hi
    mma16816(d, ah[0], ah[1], ah[2], ah[3], f.z, f.w);   // hi*lo
    mma16816(d, al[0], al[1], al[2], al[3], f.x, f.y);   // lo*hi
}

// =============================== Kernel A ===============================
__global__ void __launch_bounds__(256, 3)
qnc_mlp_kernel(const float* __restrict__ x,
               const float* __restrict__ W1, const float* __restrict__ b1,
               const float* __restrict__ W2, const float* __restrict__ b2,
               const float* __restrict__ W3, const float* __restrict__ b3,
               float* __restrict__ out, int ntiles)
{
    extern __shared__ char sm[];
    float* smf = reinterpret_cast<float*>(sm);
    const int tid  = threadIdx.x;
    const int lane = tid & 31;
    const int w    = tid >> 5;
    const int g    = lane >> 2;
    const int tq   = lane & 3;

    // ---- stage weights once per CTA in fragment order ----
    for (int idx = tid; idx < NTILE * 32; idx += 256) {
        const int t  = idx >> 5;
        const int l2 = idx & 31;
        const int g2 = l2 >> 2, tq2 = l2 & 3;
        float v0, v1, v2, v3;
        if (t < 16) {                         // W1[128][12] + b1 as K-col 12
            const int n = 8 * t + g2;
            const float* r = W1 + n * NIN;
            v0 = r[2 * tq2]; v1 = r[2 * tq2 + 1];
            const int k2 = 8 + 2 * tq2;
            v2 = (k2 < NIN) ? r[k2] : ((k2 == 12) ? b1[n] : 0.f);
            v3 = (k2 + 1 < NIN) ? r[k2 + 1] : ((k2 + 1 == 12) ? b1[n] : 0.f);
        } else if (t < 48) {                  // W2[32][128]
            const int tt = t - 16, s = tt >> 2, j = tt & 3;
            const float* r = W2 + (8 * j + g2) * 128 + 16 * s;
            v0 = r[2 * tq2]; v1 = r[2 * tq2 + 1];
            v2 = r[8 + 2 * tq2]; v3 = r[9 + 2 * tq2];
        } else {                              // W3[78][32], rows 78,79 = 0
            const int tt = t - 48, s = tt / 10, j = tt - 10 * s;
            const int n = 8 * j + g2;
            if (n < 78) {
                const float* r = W3 + n * 32 + 16 * s;
                v0 = r[2 * tq2]; v1 = r[2 * tq2 + 1];
                v2 = r[8 + 2 * tq2]; v3 = r[9 + 2 * tq2];
            } else {
                v0 = v1 = v2 = v3 = 0.f;
            }
        }
        u32 h0, l0, h1, l1;
        split2(v0, v1, h0, l0);
        split2(v2, v3, h1, l1);
        *reinterpret_cast<uint4*>(sm + O_FRAG + t * 512 + l2 * 16) =
            make_uint4(h0, h1, l0, l1);
    }
    for (int i = tid; i < 32; i += 256) smf[O_B2 / 4 + i] = b2[i];
    for (int i = tid; i < 80; i += 256) smf[O_B3 / 4 + i] = (i < 78) ? b3[i] : 0.f;
    __syncthreads();

    const uint4* frag = reinterpret_cast<const uint4*>(sm + O_FRAG) + lane;

    for (int tile = blockIdx.x; tile < ntiles; tile += gridDim.x) {
        const int warp_s0 = tile * 128 + w * 16;

        // A1 fragments from x
        const float* xr  = x + (size_t)(warp_s0 + g) * NIN;
        const float* xr8 = xr + 8 * NIN;
        float2 xa = *reinterpret_cast<const float2*>(xr  + 2 * tq);
        float2 xb = *reinterpret_cast<const float2*>(xr8 + 2 * tq);
        float2 xc, xd;
        if (tq < 2) {
            xc = *reinterpret_cast<const float2*>(xr  + 8 + 2 * tq);
            xd = *reinterpret_cast<const float2*>(xr8 + 8 + 2 * tq);
        } else {
            float one = (tq == 2) ? 1.f : 0.f;    // bias col 12
            xc = make_float2(one, 0.f);
            xd = make_float2(one, 0.f);
        }
        u32 a1h[4], a1l[4];
        split2(xa.x, xa.y, a1h[0], a1l[0]);
        split2(xb.x, xb.y, a1h[1], a1l[1]);
        split2(xc.x, xc.y, a1h[2], a1l[2]);
        split2(xd.x, xd.y, a1h[3], a1l[3]);

        // fused GEMM1 -> elu -> GEMM2, one k-step (16 h1 neurons) at a time
        float acc2[4][4];
#pragma unroll
        for (int j = 0; j < 4; j++) acc2[j][0] = acc2[j][1] = acc2[j][2] = acc2[j][3] = 0.f;
#pragma unroll
        for (int s = 0; s < 8; s++) {
            float p[8];
#pragma unroll
            for (int q = 0; q < 8; q++) p[q] = 0.f;
            mma3(p,     a1h, a1l, frag[(2 * s) * 32]);
            mma3(p + 4, a1h, a1l, frag[(2 * s + 1) * 32]);
            u32 a2h4[4], a2l4[4];
            split2(elu_f(p[0]), elu_f(p[1]), a2h4[0], a2l4[0]);
            split2(elu_f(p[2]), elu_f(p[3]), a2h4[1], a2l4[1]);
            split2(elu_f(p[4]), elu_f(p[5]), a2h4[2], a2l4[2]);
            split2(elu_f(p[6]), elu_f(p[7]), a2h4[3], a2l4[3]);
#pragma unroll
            for (int j = 0; j < 4; j++)
                mma3(acc2[j], a2h4, a2l4, frag[(16 + 4 * s + j) * 32]);
        }

        // epi2: +b2, elu -> A3 fragments
        float h2e[16];
#pragma unroll
        for (int j = 0; j < 4; j++) {
            float2 bb = *reinterpret_cast<const float2*>(smf + O_B2 / 4 + 8 * j + 2 * tq);
            h2e[4 * j + 0] = elu_f(acc2[j][0] + bb.x);
            h2e[4 * j + 1] = elu_f(acc2[j][1] + bb.y);
            h2e[4 * j + 2] = elu_f(acc2[j][2] + bb.x);
            h2e[4 * j + 3] = elu_f(acc2[j][3] + bb.y);
        }
        u32 a3h[2][4], a3l[2][4];
#pragma unroll
        for (int s = 0; s < 2; s++) {
            split2(h2e[8 * s + 0], h2e[8 * s + 1], a3h[s][0], a3l[s][0]);
            split2(h2e[8 * s + 2], h2e[8 * s + 3], a3h[s][1], a3l[s][1]);
            split2(h2e[8 * s + 4], h2e[8 * s + 5], a3h[s][2], a3l[s][2]);
            split2(h2e[8 * s + 6], h2e[8 * s + 7], a3h[s][3], a3l[s][3]);
        }

        // GEMM3 in two 5-tile halves with immediate softplus + store of L
        float* o0 = out + (size_t)(warp_s0 + g) * 144;
        float* o8 = out + (size_t)(warp_s0 + g + 8) * 144;
#pragma unroll
        for (int half = 0; half < 2; half++) {
            float acc3[5][4];
#pragma unroll
            for (int j = 0; j < 5; j++) acc3[j][0] = acc3[j][1] = acc3[j][2] = acc3[j][3] = 0.f;
#pragma unroll
            for (int s = 0; s < 2; s++)
#pragma unroll
                for (int j = 0; j < 5; j++)
                    mma3(acc3[j], a3h[s], a3l[s], frag[(48 + 10 * s + 5 * half + j) * 32]);
#pragma unroll
            for (int j = 0; j < 5; j++) {
                int col = 8 * (5 * half + j) + 2 * tq;
                float2 bb = *reinterpret_cast<const float2*>(smf + O_B3 / 4 + col);
                *reinterpret_cast<float2*>(o0 + col) =
                    make_float2(softp(acc3[j][0] + bb.x), softp(acc3[j][1] + bb.y));
                *reinterpret_cast<float2*>(o8 + col) =
                    make_float2(softp(acc3[j][2] + bb.x), softp(acc3[j][3] + bb.y));
            }
        }
    }
}

// =============================== Kernel B ===============================
// warp = 16 samples; smem-staged L load + M drain; 2 lanes/sample, 6 rows each.
#define LSTR 84      // L staging stride (floats), conflict-free
#define MSTR 148     // M staging stride (floats), conflict-free
#define BWBUF 2368   // per-warp floats = 16*MSTR
#define SMEM_B (4 * BWBUF * 4)

__global__ void __launch_bounds__(128, 4)
qnc_llt_kernel(float* __restrict__ out)
{
    extern __shared__ float smb[];
    const int tid  = threadIdx.x;
    const int lane = tid & 31;
    const int w    = tid >> 5;
    float* buf = smb + w * BWBUF;

    const int s0 = blockIdx.x * 64 + w * 16;
    const int sl = lane & 15;           // sample within warp tile
    const int h  = lane >> 4;           // half selector

    // ---- stage L: lane (sl,h) loads floats [h*40, h*40+40) of sample sl ----
    const float* src = out + (size_t)(s0 + sl) * 144 + h * 40;
#pragma unroll
    for (int i = 0; i < 10; i++) {
        float4 v = *reinterpret_cast<const float4*>(src + 4 * i);
        *reinterpret_cast<float4*>(buf + sl * LSTR + h * 40 + 4 * i) = v;
    }
    __syncwarp();

    // ---- gather own sample's L (broadcast reads) ----
    float Lr[78];
    const float* Ls = buf + sl * LSTR;
#pragma unroll
    for (int i = 0; i < 19; i++) {
        float4 t4 = *reinterpret_cast<const float4*>(Ls + 4 * i);
        Lr[4 * i] = t4.x; Lr[4 * i + 1] = t4.y; Lr[4 * i + 2] = t4.z; Lr[4 * i + 3] = t4.w;
    }
    {
        float2 t2 = *reinterpret_cast<const float2*>(Ls + 76);
        Lr[76] = t2.x; Lr[77] = t2.y;
    }
    __syncwarp();                       // L fully read before M overwrites buf

    // ---- M = L L^T, 6 rows per lane, staged to smem ----
    const int r0 = h * 6;
#pragma unroll
    for (int rr = 0; rr < 6; rr++) {
        const int r = r0 + rr;
        float row[12];
#pragma unroll
        for (int c = 0; c < 12; c++) {
            const int mn = (r < c) ? r : c;
            const int ro = r * (r + 1) / 2, co = c * (c + 1) / 2;
            float acc = Lr[ro] * Lr[co];
#pragma unroll
            for (int jj = 1; jj <= mn; jj++) acc = fmaf(Lr[ro + jj], Lr[co + jj], acc);
            row[c] = acc;
        }
#pragma unroll
        for (int c4 = 0; c4 < 3; c4++)
            *reinterpret_cast<float4*>(buf + sl * MSTR + r * 12 + 4 * c4) =
                make_float4(row[4 * c4], row[4 * c4 + 1], row[4 * c4 + 2], row[4 * c4 + 3]);
    }
    __syncwarp();

    // ---- coalesced drain: 16 samples x 36 float4 = 576 / 32 lanes ----
    float4* ov = reinterpret_cast<float4*>(out + (size_t)s0 * 144);
#pragma unroll
    for (int it = 0; it < 18; it++) {
        int q = lane + 32 * it;
        int s = q / 36, i4 = q - s * 36;
        ov[(size_t)s * 36 + i4] = *reinterpret_cast<const float4*>(buf + s * MSTR + 4 * i4);
    }
}

extern "C" void kernel_launch(void* const* d_in, const int* in_sizes, int n_in,
                              void* d_out, int out_size)
{
    const float* x  = (const float*)d_in[0];
    const float* W1 = (const float*)d_in[1];
    const float* b1 = (const float*)d_in[2];
    const float* W2 = (const float*)d_in[3];
    const float* b2 = (const float*)d_in[4];
    const float* W3 = (const float*)d_in[5];
    const float* b3 = (const float*)d_in[6];
    float* out = (float*)d_out;

    const int B = in_sizes[0] / NIN;            // 262144
    const int ntiles = B / 128;                 // 2048 (128 samples per CTA pass)

    cudaFuncSetAttribute(qnc_mlp_kernel, cudaFuncAttributeMaxDynamicSharedMemorySize, SMEM_A);
    cudaFuncSetAttribute(qnc_llt_kernel, cudaFuncAttributeMaxDynamicSharedMemorySize, SMEM_B);

    qnc_mlp_kernel<<<444, 256, SMEM_A>>>(x, W1, b1, W2, b2, W3, b3, out, ntiles);
    qnc_llt_kernel<<<B / 64, 128, SMEM_B>>>(out);
}

// round 7
// speedup vs baseline: 2.8274x; 1.4005x over previous
#include <cuda_runtime.h>
#include <cuda_bf16.h>
#include <cstdint>

// QuadraticNetCholesky, R7: two kernels.
//  A: MLP via mma.sync bf16x3 (unchanged from R6, ~52us), writes L
//     (softplus out, 78+2 floats) into out[s*144+0..79].
//  B: REBUILT. Zero-padded 12x12 L in smem -> uniform 12-deep dots,
//     4 lanes/sample x 3 rows, 8 samples/warp, 20 warps/SM.

#define NIN 12
#define NTILE 68

typedef unsigned int u32;

// ---- kernel A smem (bytes) ----
#define O_FRAG 0                       // 68 tiles x 32 lanes x 16B = 34816
#define O_B2   34816                   // 32 f32
#define O_B3   34944                   // 80 f32
#define SMEM_A (34944 + 320)           // 35264

__device__ __forceinline__ u32 pack_bf16x2(float e0, float e1) {  // e0 -> low half
    u32 d;
    asm("cvt.rn.bf16x2.f32 %0, %1, %2;" : "=r"(d) : "f"(e1), "f"(e0));
    return d;
}
__device__ __forceinline__ void split2(float f0, float f1, u32& hi, u32& lo) {
    hi = pack_bf16x2(f0, f1);
    float h0 = __uint_as_float(hi << 16);
    float h1 = __uint_as_float(hi & 0xffff0000u);
    lo = pack_bf16x2(f0 - h0, f1 - h1);
}
__device__ __forceinline__ float elu_f(float p) { return p > 0.f ? p : (__expf(p) - 1.f); }
__device__ __forceinline__ float softp(float t) {
    return fmaxf(t, 0.f) + __logf(1.f + __expf(-fabsf(t)));
}

__device__ __forceinline__ void mma16816(float* d, u32 a0, u32 a1, u32 a2, u32 a3,
                                         u32 b0, u32 b1) {
    asm volatile(
        "mma.sync.aligned.m16n8k16.row.col.f32.bf16.bf16.f32 "
        "{%0,%1,%2,%3},{%4,%5,%6,%7},{%8,%9},{%0,%1,%2,%3};"
        : "+f"(d[0]), "+f"(d[1]), "+f"(d[2]), "+f"(d[3])
        : "r"(a0), "r"(a1), "r"(a2), "r"(a3), "r"(b0), "r"(b1));
}
__device__ __forceinline__ void mma3(float* d, const u32* ah, const u32* al, uint4 f) {
    mma16816(d, ah[0], ah[1], ah[2], ah[3], f.x, f.y);   // hi*hi
    mma16816(d, ah[0], ah[1], ah[2], ah[3], f.z, f.w);   // hi*lo
    mma16816(d, al[0], al[1], al[2], al[3], f.x, f.y);   // lo*hi
}

// =============================== Kernel A ===============================
__global__ void __launch_bounds__(256, 3)
qnc_mlp_kernel(const float* __restrict__ x,
               const float* __restrict__ W1, const float* __restrict__ b1,
               const float* __restrict__ W2, const float* __restrict__ b2,
               const float* __restrict__ W3, const float* __restrict__ b3,
               float* __restrict__ out, int ntiles)
{
    extern __shared__ char sm[];
    float* smf = reinterpret_cast<float*>(sm);
    const int tid  = threadIdx.x;
    const int lane = tid & 31;
    const int w    = tid >> 5;
    const int g    = lane >> 2;
    const int tq   = lane & 3;

    // ---- stage weights once per CTA in fragment order ----
    for (int idx = tid; idx < NTILE * 32; idx += 256) {
        const int t  = idx >> 5;
        const int l2 = idx & 31;
        const int g2 = l2 >> 2, tq2 = l2 & 3;
        float v0, v1, v2, v3;
        if (t < 16) {                         // W1[128][12] + b1 as K-col 12
            const int n = 8 * t + g2;
            const float* r = W1 + n * NIN;
            v0 = r[2 * tq2]; v1 = r[2 * tq2 + 1];
            const int k2 = 8 + 2 * tq2;
            v2 = (k2 < NIN) ? r[k2] : ((k2 == 12) ? b1[n] : 0.f);
            v3 = (k2 + 1 < NIN) ? r[k2 + 1] : ((k2 + 1 == 12) ? b1[n] : 0.f);
        } else if (t < 48) {                  // W2[32][128]
            const int tt = t - 16, s = tt >> 2, j = tt & 3;
            const float* r = W2 + (8 * j + g2) * 128 + 16 * s;
            v0 = r[2 * tq2]; v1 = r[2 * tq2 + 1];
            v2 = r[8 + 2 * tq2]; v3 = r[9 + 2 * tq2];
        } else {                              // W3[78][32], rows 78,79 = 0
            const int tt = t - 48, s = tt / 10, j = tt - 10 * s;
            const int n = 8 * j + g2;
            if (n < 78) {
                const float* r = W3 + n * 32 + 16 * s;
                v0 = r[2 * tq2]; v1 = r[2 * tq2 + 1];
                v2 = r[8 + 2 * tq2]; v3 = r[9 + 2 * tq2];
            } else {
                v0 = v1 = v2 = v3 = 0.f;
            }
        }
        u32 h0, l0, h1, l1;
        split2(v0, v1, h0, l0);
        split2(v2, v3, h1, l1);
        *reinterpret_cast<uint4*>(sm + O_FRAG + t * 512 + l2 * 16) =
            make_uint4(h0, h1, l0, l1);
    }
    for (int i = tid; i < 32; i += 256) smf[O_B2 / 4 + i] = b2[i];
    for (int i = tid; i < 80; i += 256) smf[O_B3 / 4 + i] = (i < 78) ? b3[i] : 0.f;
    __syncthreads();

    const uint4* frag = reinterpret_cast<const uint4*>(sm + O_FRAG) + lane;

    for (int tile = blockIdx.x; tile < ntiles; tile += gridDim.x) {
        const int warp_s0 = tile * 128 + w * 16;

        // A1 fragments from x
        const float* xr  = x + (size_t)(warp_s0 + g) * NIN;
        const float* xr8 = xr + 8 * NIN;
        float2 xa = *reinterpret_cast<const float2*>(xr  + 2 * tq);
        float2 xb = *reinterpret_cast<const float2*>(xr8 + 2 * tq);
        float2 xc, xd;
        if (tq < 2) {
            xc = *reinterpret_cast<const float2*>(xr  + 8 + 2 * tq);
            xd = *reinterpret_cast<const float2*>(xr8 + 8 + 2 * tq);
        } else {
            float one = (tq == 2) ? 1.f : 0.f;    // bias col 12
            xc = make_float2(one, 0.f);
            xd = make_float2(one, 0.f);
        }
        u32 a1h[4], a1l[4];
        split2(xa.x, xa.y, a1h[0], a1l[0]);
        split2(xb.x, xb.y, a1h[1], a1l[1]);
        split2(xc.x, xc.y, a1h[2], a1l[2]);
        split2(xd.x, xd.y, a1h[3], a1l[3]);

        // fused GEMM1 -> elu -> GEMM2, one k-step (16 h1 neurons) at a time
        float acc2[4][4];
#pragma unroll
        for (int j = 0; j < 4; j++) acc2[j][0] = acc2[j][1] = acc2[j][2] = acc2[j][3] = 0.f;
#pragma unroll
        for (int s = 0; s < 8; s++) {
            float p[8];
#pragma unroll
            for (int q = 0; q < 8; q++) p[q] = 0.f;
            mma3(p,     a1h, a1l, frag[(2 * s) * 32]);
            mma3(p + 4, a1h, a1l, frag[(2 * s + 1) * 32]);
            u32 a2h4[4], a2l4[4];
            split2(elu_f(p[0]), elu_f(p[1]), a2h4[0], a2l4[0]);
            split2(elu_f(p[2]), elu_f(p[3]), a2h4[1], a2l4[1]);
            split2(elu_f(p[4]), elu_f(p[5]), a2h4[2], a2l4[2]);
            split2(elu_f(p[6]), elu_f(p[7]), a2h4[3], a2l4[3]);
#pragma unroll
            for (int j = 0; j < 4; j++)
                mma3(acc2[j], a2h4, a2l4, frag[(16 + 4 * s + j) * 32]);
        }

        // epi2: +b2, elu -> A3 fragments
        float h2e[16];
#pragma unroll
        for (int j = 0; j < 4; j++) {
            float2 bb = *reinterpret_cast<const float2*>(smf + O_B2 / 4 + 8 * j + 2 * tq);
            h2e[4 * j + 0] = elu_f(acc2[j][0] + bb.x);
            h2e[4 * j + 1] = elu_f(acc2[j][1] + bb.y);
            h2e[4 * j + 2] = elu_f(acc2[j][2] + bb.x);
            h2e[4 * j + 3] = elu_f(acc2[j][3] + bb.y);
        }
        u32 a3h[2][4], a3l[2][4];
#pragma unroll
        for (int s = 0; s < 2; s++) {
            split2(h2e[8 * s + 0], h2e[8 * s + 1], a3h[s][0], a3l[s][0]);
            split2(h2e[8 * s + 2], h2e[8 * s + 3], a3h[s][1], a3l[s][1]);
            split2(h2e[8 * s + 4], h2e[8 * s + 5], a3h[s][2], a3l[s][2]);
            split2(h2e[8 * s + 6], h2e[8 * s + 7], a3h[s][3], a3l[s][3]);
        }

        // GEMM3 in two 5-tile halves with immediate softplus + store of L
        float* o0 = out + (size_t)(warp_s0 + g) * 144;
        float* o8 = out + (size_t)(warp_s0 + g + 8) * 144;
#pragma unroll
        for (int half = 0; half < 2; half++) {
            float acc3[5][4];
#pragma unroll
            for (int j = 0; j < 5; j++) acc3[j][0] = acc3[j][1] = acc3[j][2] = acc3[j][3] = 0.f;
#pragma unroll
            for (int s = 0; s < 2; s++)
#pragma unroll
                for (int j = 0; j < 5; j++)
                    mma3(acc3[j], a3h[s], a3l[s], frag[(48 + 10 * s + 5 * half + j) * 32]);
#pragma unroll
            for (int j = 0; j < 5; j++) {
                int col = 8 * (5 * half + j) + 2 * tq;
                float2 bb = *reinterpret_cast<const float2*>(smf + O_B3 / 4 + col);
                *reinterpret_cast<float2*>(o0 + col) =
                    make_float2(softp(acc3[j][0] + bb.x), softp(acc3[j][1] + bb.y));
                *reinterpret_cast<float2*>(o8 + col) =
                    make_float2(softp(acc3[j][2] + bb.x), softp(acc3[j][3] + bb.y));
            }
        }
    }
}

// =============================== Kernel B ===============================
// Padded-L design: per sample, L scattered into a zero-padded 12x12 lower-tri
// matrix in smem (stride 148 floats/sample = 4*37: vector-aligned AND
// conflict-free). M[r][c] = sum_{j=0..11} Lpad[r][j]*Lpad[c][j] exactly.
// 4 lanes/sample (3 rows each), 8 samples/warp, buffer reused L -> M.

#define BSTR 148                          // floats per sample slot
#define BWARP (8 * BSTR)                  // 1184 floats per warp
#define SMEM_B (4 * BWARP * 4 + 192)      // 19136 B

__global__ void __launch_bounds__(128, 5)
qnc_llt_kernel(float* __restrict__ out)
{
    extern __shared__ float smb[];
    unsigned short* OFF = reinterpret_cast<unsigned short*>(smb + 4 * BWARP);
    const int tid  = threadIdx.x;
    const int lane = tid & 31;
    const int w    = tid >> 5;

    // tri-index f -> padded offset r*12+j (table built once per CTA)
    if (tid < 78) {
        float ff = (float)tid;
        int r = (int)((sqrtf(8.f * ff + 1.f) - 1.f) * 0.5f);
        OFF[tid] = (unsigned short)(r * 12 + tid - (r * (r + 1)) / 2);
    }
    __syncthreads();

    float* buf = smb + w * BWARP;
    const int s0 = blockIdx.x * 32 + w * 8;

    // ---- zero-fill padded region (8 samples x 144 floats) ----
#pragma unroll
    for (int it = 0; it < 9; it++) {
        int q = lane + 32 * it;
        int sq = q / 36, i4 = q % 36;
        *reinterpret_cast<float4*>(&buf[sq * BSTR + 4 * i4]) = make_float4(0.f, 0.f, 0.f, 0.f);
    }
    __syncwarp();

    // ---- coalesced L load + scatter into padded layout ----
#pragma unroll
    for (int it = 0; it < 5; it++) {
        int q = lane + 32 * it;
        int sq = q / 20, i4 = q % 20;
        float4 v = *reinterpret_cast<const float4*>(out + (size_t)(s0 + sq) * 144 + 4 * i4);
        int f = 4 * i4;
        float* bs = buf + sq * BSTR;
        if (f     < 78) bs[OFF[f]]     = v.x;
        if (f + 1 < 78) bs[OFF[f + 1]] = v.y;
        if (f + 2 < 78) bs[OFF[f + 2]] = v.z;
        if (f + 3 < 78) bs[OFF[f + 3]] = v.w;
    }
    __syncwarp();

    // ---- compute: lane (sq, qr) does rows 3qr..3qr+2 of sample sq ----
    const int sq = lane >> 2;
    const int qr = lane & 3;
    const float* Ls = buf + sq * BSTR;

    float a[36];
#pragma unroll
    for (int i = 0; i < 3; i++)
#pragma unroll
        for (int k = 0; k < 3; k++)
            *reinterpret_cast<float4*>(&a[i * 12 + 4 * k]) =
                *reinterpret_cast<const float4*>(&Ls[(3 * qr + i) * 12 + 4 * k]);

    float m[36];
#pragma unroll
    for (int c = 0; c < 12; c++) {
        float bv[12];
#pragma unroll
        for (int k = 0; k < 3; k++)
            *reinterpret_cast<float4*>(&bv[4 * k]) =
                *reinterpret_cast<const float4*>(&Ls[c * 12 + 4 * k]);
#pragma unroll
        for (int i = 0; i < 3; i++) {
            float acc = a[i * 12] * bv[0];
#pragma unroll
            for (int j = 1; j < 12; j++) acc = fmaf(a[i * 12 + j], bv[j], acc);
            m[i * 12 + c] = acc;
        }
    }
    __syncwarp();                          // all Lpad reads done before overwrite

    // ---- store M over the same buffer ----
    float* Ms = buf + sq * BSTR;
#pragma unroll
    for (int i = 0; i < 3; i++)
#pragma unroll
        for (int k = 0; k < 3; k++)
            *reinterpret_cast<float4*>(&Ms[(3 * qr + i) * 12 + 4 * k]) =
                *reinterpret_cast<const float4*>(&m[i * 12 + 4 * k]);
    __syncwarp();

    // ---- coalesced drain ----
#pragma unroll
    for (int it = 0; it < 9; it++) {
        int q = lane + 32 * it;
        int sq2 = q / 36, i4 = q % 36;
        *reinterpret_cast<float4*>(out + (size_t)(s0 + sq2) * 144 + 4 * i4) =
            *reinterpret_cast<const float4*>(&buf[sq2 * BSTR + 4 * i4]);
    }
}

extern "C" void kernel_launch(void* const* d_in, const int* in_sizes, int n_in,
                              void* d_out, int out_size)
{
    const float* x  = (const float*)d_in[0];
    const float* W1 = (const float*)d_in[1];
    const float* b1 = (const float*)d_in[2];
    const float* W2 = (const float*)d_in[3];
    const float* b2 = (const float*)d_in[4];
    const float* W3 = (const float*)d_in[5];
    const float* b3 = (const float*)d_in[6];
    float* out = (float*)d_out;

    const int B = in_sizes[0] / NIN;            // 262144
    const int ntiles = B / 128;                 // 2048 (128 samples per CTA pass)

    cudaFuncSetAttribute(qnc_mlp_kernel, cudaFuncAttributeMaxDynamicSharedMemorySize, SMEM_A);
    cudaFuncSetAttribute(qnc_llt_kernel, cudaFuncAttributeMaxDynamicSharedMemorySize, SMEM_B);

    qnc_mlp_kernel<<<444, 256, SMEM_A>>>(x, W1, b1, W2, b2, W3, b3, out, ntiles);
    qnc_llt_kernel<<<B / 32, 128, SMEM_B>>>(out);
}